// round 1
// baseline (speedup 1.0000x reference)
#include <cuda_runtime.h>

// FlashAttentionImpl: B=2, H=16, S=4096, D=64, fp32, non-causal.
// Replicates the reference's exact (non-standard) online recurrence:
//   exp_scores = exp(scores - block_max)   [block max, NOT running max]
//   o = o*exp(m_old - m_new) + exp_scores @ V
//   n = n*exp(m_old - m_new) + rowsum(exp_scores)
//   out = o / (n + 1e-6)
// Block size along K MUST be 128 and processed in order to match numerics.

#define SEQ      4096
#define HD       64
#define BM       64          // query rows per CTA
#define BN       128         // key block (fixed by reference semantics)
#define NTHREADS 256
#define SCALE    0.125f      // 1/sqrt(64)

#define SMEM_FLOATS (BM*HD + HD*BN + BN*HD + BM*BN)   // Qs + Kt + Vs + Ss
#define SMEM_BYTES  (SMEM_FLOATS * 4)                 // 114688

__global__ __launch_bounds__(NTHREADS)
void fa_kernel(const float* __restrict__ q,
               const float* __restrict__ k,
               const float* __restrict__ v,
               float* __restrict__ out)
{
    extern __shared__ float sm[];
    float* Qs = sm;                     // [BM][HD]  row-major (pre-scaled)
    float* Kt = Qs + BM * HD;           // [HD][BN]  d-major (transposed K block)
    float* Vs = Kt + HD * BN;           // [BN][HD]  row-major
    float* Ss = Vs + BN * HD;           // [BM][BN]  exp-scores

    const int tid = threadIdx.x;
    const int tx  = tid & 15;           // 0..15  -> 8 score cols / 4 out cols
    const int ty  = tid >> 4;           // 0..15  -> 4 rows (one half-warp owns 4 rows)
    const int bh  = blockIdx.y;
    const int qb  = blockIdx.x;

    const float* qg  = q + ((size_t)bh * SEQ + (size_t)qb * BM) * HD;
    const float* kg0 = k + (size_t)bh * SEQ * HD;
    const float* vg0 = v + (size_t)bh * SEQ * HD;
    float*       og  = out + ((size_t)bh * SEQ + (size_t)qb * BM) * HD;

    // ---- load Q once, fold in softmax scale ----
    #pragma unroll
    for (int i = 0; i < 4; i++) {
        int idx = tid + i * NTHREADS;                 // 1024 float4 total
        float4 t = ((const float4*)qg)[idx];
        t.x *= SCALE; t.y *= SCALE; t.z *= SCALE; t.w *= SCALE;
        ((float4*)Qs)[idx] = t;
    }

    float oacc[4][4];
    float m_i[4], n_i[4];
    #pragma unroll
    for (int i = 0; i < 4; i++) {
        m_i[i] = -1e30f;
        n_i[i] = 0.f;
        #pragma unroll
        for (int j = 0; j < 4; j++) oacc[i][j] = 0.f;
    }

    for (int blk = 0; blk < SEQ / BN; blk++) {
        __syncthreads();   // protect Vs/Ss from previous iteration
        const float* kg = kg0 + (size_t)blk * BN * HD;
        const float* vg = vg0 + (size_t)blk * BN * HD;

        // ---- load K (transposed to d-major) and V (row-major) ----
        #pragma unroll
        for (int i = 0; i < 8; i++) {
            int idx = tid + i * NTHREADS;             // 0..2047
            int dg  = idx >> 7;                       // 0..15 (d group of 4)
            int col = idx & 127;                      // key index in block
            float4 kk4 = ((const float4*)(kg + (size_t)col * HD))[dg];
            int d0 = dg * 4;
            Kt[(d0 + 0) * BN + col] = kk4.x;
            Kt[(d0 + 1) * BN + col] = kk4.y;
            Kt[(d0 + 2) * BN + col] = kk4.z;
            Kt[(d0 + 3) * BN + col] = kk4.w;
            ((float4*)Vs)[idx] = ((const float4*)vg)[idx];
        }
        __syncthreads();

        // ---- Phase A: scores = Qs @ Kt  (4x8 register tile per thread) ----
        float acc[4][8];
        #pragma unroll
        for (int i = 0; i < 4; i++)
            #pragma unroll
            for (int j = 0; j < 8; j++) acc[i][j] = 0.f;

        const float* qr = Qs + (ty * 4) * HD;
        #pragma unroll 4
        for (int kk = 0; kk < HD; kk++) {
            float qv[4];
            qv[0] = qr[kk];
            qv[1] = qr[HD + kk];
            qv[2] = qr[2 * HD + kk];
            qv[3] = qr[3 * HD + kk];
            float4 ka = *(const float4*)(Kt + kk * BN + tx * 8);
            float4 kc = *(const float4*)(Kt + kk * BN + tx * 8 + 4);
            float kr[8] = {ka.x, ka.y, ka.z, ka.w, kc.x, kc.y, kc.z, kc.w};
            #pragma unroll
            for (int i = 0; i < 4; i++)
                #pragma unroll
                for (int j = 0; j < 8; j++)
                    acc[i][j] += qv[i] * kr[j];
        }

        // ---- online softmax (reference's exact recurrence) ----
        #pragma unroll
        for (int i = 0; i < 4; i++) {
            float mx = acc[i][0];
            #pragma unroll
            for (int j = 1; j < 8; j++) mx = fmaxf(mx, acc[i][j]);
            #pragma unroll
            for (int off = 8; off > 0; off >>= 1)
                mx = fmaxf(mx, __shfl_xor_sync(0xffffffffu, mx, off, 16));
            // mx == block_max for this row (all 16 lanes agree)
            float newm = fmaxf(m_i[i], mx);
            float esc  = __expf(m_i[i] - newm);
            float rs = 0.f;
            #pragma unroll
            for (int j = 0; j < 8; j++) {
                float e = __expf(acc[i][j] - mx);   // minus BLOCK max (reference quirk)
                acc[i][j] = e;
                rs += e;
            }
            #pragma unroll
            for (int off = 8; off > 0; off >>= 1)
                rs += __shfl_xor_sync(0xffffffffu, rs, off, 16);
            n_i[i] = n_i[i] * esc + rs;
            m_i[i] = newm;
            #pragma unroll
            for (int j = 0; j < 4; j++) oacc[i][j] *= esc;

            *(float4*)(Ss + (ty * 4 + i) * BN + tx * 8) =
                make_float4(acc[i][0], acc[i][1], acc[i][2], acc[i][3]);
            *(float4*)(Ss + (ty * 4 + i) * BN + tx * 8 + 4) =
                make_float4(acc[i][4], acc[i][5], acc[i][6], acc[i][7]);
        }
        // rows ty*4..ty*4+3 are written and read by the same half-warp only
        __syncwarp();

        // ---- Phase B: oacc += exp_scores @ V  (4x4 register tile) ----
        const float* sr = Ss + (ty * 4) * BN;
        const float* vb = Vs + tx * 4;
        #pragma unroll 4
        for (int kk = 0; kk < BN; kk++) {
            float4 vv = *(const float4*)(vb + kk * HD);
            float s0 = sr[kk];
            float s1 = sr[BN + kk];
            float s2 = sr[2 * BN + kk];
            float s3 = sr[3 * BN + kk];
            oacc[0][0] += s0 * vv.x; oacc[0][1] += s0 * vv.y;
            oacc[0][2] += s0 * vv.z; oacc[0][3] += s0 * vv.w;
            oacc[1][0] += s1 * vv.x; oacc[1][1] += s1 * vv.y;
            oacc[1][2] += s1 * vv.z; oacc[1][3] += s1 * vv.w;
            oacc[2][0] += s2 * vv.x; oacc[2][1] += s2 * vv.y;
            oacc[2][2] += s2 * vv.z; oacc[2][3] += s2 * vv.w;
            oacc[3][0] += s3 * vv.x; oacc[3][1] += s3 * vv.y;
            oacc[3][2] += s3 * vv.z; oacc[3][3] += s3 * vv.w;
        }
    }

    // ---- epilogue: out = o / (n + 1e-6) ----
    #pragma unroll
    for (int i = 0; i < 4; i++) {
        float inv = 1.f / (n_i[i] + 1e-6f);
        float4 r = make_float4(oacc[i][0] * inv, oacc[i][1] * inv,
                               oacc[i][2] * inv, oacc[i][3] * inv);
        *(float4*)(og + (ty * 4 + i) * HD + tx * 4) = r;
    }
}

extern "C" void kernel_launch(void* const* d_in, const int* in_sizes, int n_in,
                              void* d_out, int out_size)
{
    const float* q = (const float*)d_in[0];
    const float* k = (const float*)d_in[1];
    const float* v = (const float*)d_in[2];
    float* o = (float*)d_out;

    int n_bh = in_sizes[0] / (SEQ * HD);   // B*H = 32

    // idempotent, host-side config (not a stream op; safe under graph capture)
    cudaFuncSetAttribute(fa_kernel, cudaFuncAttributeMaxDynamicSharedMemorySize,
                         SMEM_BYTES);

    dim3 grid(SEQ / BM, n_bh);
    fa_kernel<<<grid, NTHREADS, SMEM_BYTES>>>(q, k, v, o);
}

// round 2
// speedup vs baseline: 4.4192x; 4.4192x over previous
#include <cuda_runtime.h>
#include <cuda_bf16.h>
#include <cstdint>

// FlashAttention B=2,H=16,S=4096,D=64 fp32, non-causal.
// Reference's exact recurrence (block_max variant), BN=128 fixed, in order.
// Tensor-core path: mma.sync m16n8k16 bf16, 3-term hi/lo split (~fp32 accuracy).

#define SEQ   4096
#define HD    64
#define BM    128
#define BN    128
#define NTHR  256
#define NBLK  (SEQ / BN)        // 32
#define SCALE 0.125f

#define NTOT  (2 * 16 * SEQ * HD)   // 8388608 elems per tensor

// bf16 hi/lo scratch (static device arrays: allocation-free)
__device__ __nv_bfloat16 g_qh[NTOT];
__device__ __nv_bfloat16 g_ql[NTOT];
__device__ __nv_bfloat16 g_kh[NTOT];
__device__ __nv_bfloat16 g_kl[NTOT];
__device__ __nv_bfloat16 g_vh[NTOT];
__device__ __nv_bfloat16 g_vl[NTOT];

// ---------------- converter: fp32 -> bf16 hi/lo ----------------
__device__ __forceinline__ void split4(float4 t, float s,
                                       __nv_bfloat16* hp, __nv_bfloat16* lp)
{
    float x0 = t.x * s, x1 = t.y * s, x2 = t.z * s, x3 = t.w * s;
    __nv_bfloat16 h0 = __float2bfloat16_rn(x0);
    __nv_bfloat16 h1 = __float2bfloat16_rn(x1);
    __nv_bfloat16 h2 = __float2bfloat16_rn(x2);
    __nv_bfloat16 h3 = __float2bfloat16_rn(x3);
    __nv_bfloat16 l0 = __float2bfloat16_rn(x0 - __bfloat162float(h0));
    __nv_bfloat16 l1 = __float2bfloat16_rn(x1 - __bfloat162float(h1));
    __nv_bfloat16 l2 = __float2bfloat16_rn(x2 - __bfloat162float(h2));
    __nv_bfloat16 l3 = __float2bfloat16_rn(x3 - __bfloat162float(h3));
    __nv_bfloat162 hA; hA.x = h0; hA.y = h1;
    __nv_bfloat162 hB; hB.x = h2; hB.y = h3;
    __nv_bfloat162 lA; lA.x = l0; lA.y = l1;
    __nv_bfloat162 lB; lB.x = l2; lB.y = l3;
    uint2 hu = make_uint2(*(uint32_t*)&hA, *(uint32_t*)&hB);
    uint2 lu = make_uint2(*(uint32_t*)&lA, *(uint32_t*)&lB);
    *(uint2*)hp = hu;
    *(uint2*)lp = lu;
}

__global__ __launch_bounds__(512)
void cvt_kernel(const float* __restrict__ q,
                const float* __restrict__ k,
                const float* __restrict__ v)
{
    int i = blockIdx.x * blockDim.x + threadIdx.x;   // one float4 group
    if (i >= NTOT / 4) return;
    split4(((const float4*)q)[i], SCALE, g_qh + 4 * i, g_ql + 4 * i);
    split4(((const float4*)k)[i], 1.0f,  g_kh + 4 * i, g_kl + 4 * i);
    split4(((const float4*)v)[i], 1.0f,  g_vh + 4 * i, g_vl + 4 * i);
}

// ---------------- main attention kernel ----------------
// smem (bf16 elems): Qh[128*64], Ql[128*64], then 2 stages of
// {Kh,Kl,Vh,Vl}[128*64] each.
#define TILE_E   (BM * HD)                 // 8192 bf16 = 16KB
#define OFF_QH   0
#define OFF_QL   TILE_E
#define OFF_ST0  (2 * TILE_E)
#define STAGE_E  (4 * TILE_E)
#define SMEM_BYTES ((2 * TILE_E + 2 * STAGE_E) * 2)   // 163840

// swizzled byte offset of 16B chunk (row in [0,128), chunk in [0,8))
__device__ __forceinline__ uint32_t swz(uint32_t row, uint32_t ch)
{
    return (row * 8u + (ch ^ (row & 7u))) * 16u;
}

__device__ __forceinline__ void cp16(uint32_t dst, const void* src)
{
    asm volatile("cp.async.cg.shared.global [%0], [%1], 16;\n"
                 :: "r"(dst), "l"(src));
}
__device__ __forceinline__ void cp_commit()
{
    asm volatile("cp.async.commit_group;\n");
}
__device__ __forceinline__ void cp_wait1()
{
    asm volatile("cp.async.wait_group 1;\n");
}
__device__ __forceinline__ void cp_wait0()
{
    asm volatile("cp.async.wait_group 0;\n");
}

__device__ __forceinline__ void ldm_x4(uint32_t a, uint32_t& r0, uint32_t& r1,
                                       uint32_t& r2, uint32_t& r3)
{
    asm volatile("ldmatrix.sync.aligned.m8n8.x4.shared.b16 {%0,%1,%2,%3}, [%4];\n"
                 : "=r"(r0), "=r"(r1), "=r"(r2), "=r"(r3) : "r"(a));
}
__device__ __forceinline__ void ldm_x2(uint32_t a, uint32_t& r0, uint32_t& r1)
{
    asm volatile("ldmatrix.sync.aligned.m8n8.x2.shared.b16 {%0,%1}, [%2];\n"
                 : "=r"(r0), "=r"(r1) : "r"(a));
}
__device__ __forceinline__ void ldm_x2t(uint32_t a, uint32_t& r0, uint32_t& r1)
{
    asm volatile("ldmatrix.sync.aligned.m8n8.x2.trans.shared.b16 {%0,%1}, [%2];\n"
                 : "=r"(r0), "=r"(r1) : "r"(a));
}

__device__ __forceinline__ void mma_bf16(float* c, const uint32_t* a,
                                         const uint32_t* b)
{
    asm volatile(
        "mma.sync.aligned.m16n8k16.row.col.f32.bf16.bf16.f32 "
        "{%0,%1,%2,%3}, {%4,%5,%6,%7}, {%8,%9}, {%0,%1,%2,%3};\n"
        : "+f"(c[0]), "+f"(c[1]), "+f"(c[2]), "+f"(c[3])
        : "r"(a[0]), "r"(a[1]), "r"(a[2]), "r"(a[3]), "r"(b[0]), "r"(b[1]));
}

__device__ __forceinline__ uint32_t pack2(float a, float b)
{
    __nv_bfloat162 t;
    t.x = __float2bfloat16_rn(a);
    t.y = __float2bfloat16_rn(b);
    return *(uint32_t*)&t;
}

__global__ __launch_bounds__(NTHR, 1)
void fa2_kernel(float* __restrict__ out)
{
    extern __shared__ __align__(16) unsigned char smraw[];
    uint32_t sbase = (uint32_t)__cvta_generic_to_shared(smraw);

    const int tid  = threadIdx.x;
    const int lane = tid & 31;
    const int w    = tid >> 5;          // warp 0..7 -> rows w*16..w*16+15
    const int bh   = blockIdx.y;
    const int qb   = blockIdx.x;

    const uint32_t qsmh = sbase + OFF_QH * 2;
    const uint32_t qsml = sbase + OFF_QL * 2;

    // ---- stage Q (hi/lo) into swizzled smem ----
    {
        const __nv_bfloat16* qh = g_qh + ((size_t)bh * SEQ + (size_t)qb * BM) * HD;
        const __nv_bfloat16* ql = g_ql + ((size_t)bh * SEQ + (size_t)qb * BM) * HD;
        #pragma unroll
        for (int i = 0; i < 4; i++) {
            int cid = tid + i * NTHR;        // 0..1023
            int row = cid >> 3, ch = cid & 7;
            uint32_t d = swz(row, ch);
            *(uint4*)(smraw + OFF_QH * 2 + d) = *(const uint4*)(qh + row * HD + ch * 8);
            *(uint4*)(smraw + OFF_QL * 2 + d) = *(const uint4*)(ql + row * HD + ch * 8);
        }
    }

    // ---- issue cp.async for K/V blocks 0 and 1 ----
    const size_t kvbase = (size_t)bh * SEQ * HD;
    auto stage_load = [&](int blk) {
        int st = blk & 1;
        uint32_t sb = sbase + (OFF_ST0 + st * STAGE_E) * 2;
        size_t gb = kvbase + (size_t)blk * BN * HD;
        #pragma unroll
        for (int i = 0; i < 4; i++) {
            int cid = tid + i * NTHR;
            int row = cid >> 3, ch = cid & 7;
            uint32_t d = swz(row, ch);
            size_t g = gb + (size_t)row * HD + ch * 8;
            cp16(sb + 0 * TILE_E * 2 + d, g_kh + g);
            cp16(sb + 1 * TILE_E * 2 + d, g_kl + g);
            cp16(sb + 2 * TILE_E * 2 + d, g_vh + g);
            cp16(sb + 3 * TILE_E * 2 + d, g_vl + g);
        }
        cp_commit();
    };
    stage_load(0);
    stage_load(1);

    __syncthreads();   // Q smem visible

    // ---- load Q fragments (held in registers for all 32 blocks) ----
    uint32_t qfh[4][4], qfl[4][4];
    {
        int quad = lane >> 3, i = lane & 7;
        int row = w * 16 + (quad & 1) * 8 + i;
        #pragma unroll
        for (int t = 0; t < 4; t++) {
            uint32_t a = swz(row, 2 * t + (quad >> 1));
            ldm_x4(qsmh + a, qfh[t][0], qfh[t][1], qfh[t][2], qfh[t][3]);
            ldm_x4(qsml + a, qfl[t][0], qfl[t][1], qfl[t][2], qfl[t][3]);
        }
    }

    float o[8][4];
    #pragma unroll
    for (int n = 0; n < 8; n++)
        #pragma unroll
        for (int r = 0; r < 4; r++) o[n][r] = 0.f;
    float m0 = -1e30f, m1 = -1e30f, nr0 = 0.f, nr1 = 0.f;

    const int li = lane & 15;

    for (int blk = 0; blk < NBLK; blk++) {
        if (blk < NBLK - 2) cp_wait1(); else cp_wait0();
        __syncthreads();

        int st = blk & 1;
        uint32_t kh_b = sbase + (OFF_ST0 + st * STAGE_E + 0 * TILE_E) * 2;
        uint32_t kl_b = sbase + (OFF_ST0 + st * STAGE_E + 1 * TILE_E) * 2;
        uint32_t vh_b = sbase + (OFF_ST0 + st * STAGE_E + 2 * TILE_E) * 2;
        uint32_t vl_b = sbase + (OFF_ST0 + st * STAGE_E + 3 * TILE_E) * 2;

        // ---- QK^T: scores c[16 n-tiles][4] ----
        float c[16][4];
        #pragma unroll
        for (int j = 0; j < 16; j++) {
            c[j][0] = c[j][1] = c[j][2] = c[j][3] = 0.f;
            int row = 8 * j + (li & 7);
            #pragma unroll
            for (int t = 0; t < 4; t++) {
                uint32_t a = swz(row, 2 * t + (li >> 3));
                uint32_t bh2[2], bl2[2];
                ldm_x2(kh_b + a, bh2[0], bh2[1]);
                ldm_x2(kl_b + a, bl2[0], bl2[1]);
                mma_bf16(c[j], qfh[t], bh2);
                mma_bf16(c[j], qfh[t], bl2);
                mma_bf16(c[j], qfl[t], bh2);
            }
        }

        // ---- online softmax (reference recurrence, block max) ----
        float mx0 = -1e30f, mx1 = -1e30f;
        #pragma unroll
        for (int j = 0; j < 16; j++) {
            mx0 = fmaxf(mx0, fmaxf(c[j][0], c[j][1]));
            mx1 = fmaxf(mx1, fmaxf(c[j][2], c[j][3]));
        }
        mx0 = fmaxf(mx0, __shfl_xor_sync(0xffffffffu, mx0, 1));
        mx0 = fmaxf(mx0, __shfl_xor_sync(0xffffffffu, mx0, 2));
        mx1 = fmaxf(mx1, __shfl_xor_sync(0xffffffffu, mx1, 1));
        mx1 = fmaxf(mx1, __shfl_xor_sync(0xffffffffu, mx1, 2));

        float nm0 = fmaxf(m0, mx0), nm1 = fmaxf(m1, mx1);
        float e0 = __expf(m0 - nm0), e1 = __expf(m1 - nm1);
        m0 = nm0; m1 = nm1;

        float rs0 = 0.f, rs1 = 0.f;
        #pragma unroll
        for (int j = 0; j < 16; j++) {
            c[j][0] = __expf(c[j][0] - mx0);
            c[j][1] = __expf(c[j][1] - mx0);
            c[j][2] = __expf(c[j][2] - mx1);
            c[j][3] = __expf(c[j][3] - mx1);
            rs0 += c[j][0] + c[j][1];
            rs1 += c[j][2] + c[j][3];
        }
        rs0 += __shfl_xor_sync(0xffffffffu, rs0, 1);
        rs0 += __shfl_xor_sync(0xffffffffu, rs0, 2);
        rs1 += __shfl_xor_sync(0xffffffffu, rs1, 1);
        rs1 += __shfl_xor_sync(0xffffffffu, rs1, 2);
        nr0 = nr0 * e0 + rs0;
        nr1 = nr1 * e1 + rs1;

        #pragma unroll
        for (int n = 0; n < 8; n++) {
            o[n][0] *= e0; o[n][1] *= e0;
            o[n][2] *= e1; o[n][3] *= e1;
        }

        // ---- PV: o += exp_scores @ V (P hi/lo in regs from C frags) ----
        #pragma unroll
        for (int t = 0; t < 8; t++) {       // k-tile: keys 16t..16t+15
            uint32_t pah[4], pal[4];
            #pragma unroll
            for (int h = 0; h < 2; h++) {   // sub n-tile 2t+h
                int j = 2 * t + h;
                float x0 = c[j][0], x1 = c[j][1], x2 = c[j][2], x3 = c[j][3];
                uint32_t h01 = pack2(x0, x1);
                uint32_t h23 = pack2(x2, x3);
                __nv_bfloat162 hv01 = *(__nv_bfloat162*)&h01;
                __nv_bfloat162 hv23 = *(__nv_bfloat162*)&h23;
                pah[2 * h + 0] = h01;
                pah[2 * h + 1] = h23;
                pal[2 * h + 0] = pack2(x0 - __bfloat162float(hv01.x),
                                       x1 - __bfloat162float(hv01.y));
                pal[2 * h + 1] = pack2(x2 - __bfloat162float(hv23.x),
                                       x3 - __bfloat162float(hv23.y));
            }
            // hmm: A-frag order is a0=(r,k0..),a1=(r+8,k0..),a2=(r,k8..),a3=(r+8,k8..)
            // built above as [j=2t: a0,a1][j=2t+1: a2,a3] -> correct.
            int vrow = 16 * t + li;
            #pragma unroll
            for (int n = 0; n < 8; n++) {   // d-tile
                uint32_t a = swz(vrow, n ^ (vrow & 7));
                // note swz takes (row, logical ch); inline XOR here:
                a = (vrow * 8u + ((uint32_t)n ^ (vrow & 7u))) * 16u;
                uint32_t bvh[2], bvl[2];
                ldm_x2t(vh_b + a, bvh[0], bvh[1]);
                ldm_x2t(vl_b + a, bvl[0], bvl[1]);
                mma_bf16(o[n], pah, bvh);
                mma_bf16(o[n], pah, bvl);
                mma_bf16(o[n], pal, bvh);
            }
        }

        __syncthreads();                    // all warps done with stage st
        if (blk + 2 < NBLK) stage_load(blk + 2);
    }

    // ---- epilogue ----
    float inv0 = 1.f / (nr0 + 1e-6f);
    float inv1 = 1.f / (nr1 + 1e-6f);
    int r  = lane >> 2;
    int cb = (lane & 3) * 2;
    float* og0 = out + ((size_t)bh * SEQ + (size_t)qb * BM + w * 16 + r) * HD;
    float* og1 = og0 + 8 * HD;
    #pragma unroll
    for (int n = 0; n < 8; n++) {
        *(float2*)(og0 + n * 8 + cb) = make_float2(o[n][0] * inv0, o[n][1] * inv0);
        *(float2*)(og1 + n * 8 + cb) = make_float2(o[n][2] * inv1, o[n][3] * inv1);
    }
}

extern "C" void kernel_launch(void* const* d_in, const int* in_sizes, int n_in,
                              void* d_out, int out_size)
{
    const float* q = (const float*)d_in[0];
    const float* k = (const float*)d_in[1];
    const float* v = (const float*)d_in[2];
    float* o = (float*)d_out;

    int n_bh = in_sizes[0] / (SEQ * HD);    // 32

    cudaFuncSetAttribute(fa2_kernel, cudaFuncAttributeMaxDynamicSharedMemorySize,
                         SMEM_BYTES);

    cvt_kernel<<<(NTOT / 4 + 511) / 512, 512>>>(q, k, v);
    dim3 grid(SEQ / BM, n_bh);
    fa2_kernel<<<grid, NTHR, SMEM_BYTES>>>(o);
}